// round 1
// baseline (speedup 1.0000x reference)
#include <cuda_runtime.h>
#include <cstdint>

// Problem constants
constexpr int cB = 2;
constexpr int cT = 2048;
constexpr int cE = 1024;
constexpr int cH = 16;
constexpr int cD = 64;
constexpr int cM = cB * cT;  // 4096 rows

// Scratch (allocation-free requirement -> __device__ globals)
__device__ float g_Q[(size_t)cM * cE];
__device__ float g_K[(size_t)cM * cE];
__device__ float g_V[(size_t)cM * cE];
__device__ float g_A[(size_t)cM * cE];

// ---------------------------------------------------------------------------
// SGEMM: Y[M,N] = X[M,K] @ W[N,K]^T + bias[N]
// M = 4096, N = K = 1024. Block computes a 128x128 tile, BK=8,
// 16x16 threads, 8x8 register tile each. Shared tiles stored k-major
// (transposed on load) with +4 pad to kill store-side bank conflicts.
// ---------------------------------------------------------------------------
__global__ __launch_bounds__(256) void sgemm_nt_bias(
    const float* __restrict__ X, const float* __restrict__ W,
    const float* __restrict__ bias, float* __restrict__ Y)
{
    constexpr int N = 1024;
    constexpr int Kd = 1024;
    __shared__ float Xs[8][132];
    __shared__ float Ws[8][132];

    const int tid = threadIdx.x;        // 0..255
    const int tx = tid & 15;
    const int ty = tid >> 4;
    const int row0 = blockIdx.y * 128;
    const int col0 = blockIdx.x * 128;

    // Load mapping: each thread loads one float4 along K for X and W
    const int lm = tid >> 1;            // 0..127 row within tile
    const int lk = (tid & 1) * 4;       // 0 or 4
    const float* Xg = X + (size_t)(row0 + lm) * Kd + lk;
    const float* Wg = W + (size_t)(col0 + lm) * Kd + lk;

    float acc[8][8];
#pragma unroll
    for (int i = 0; i < 8; i++)
#pragma unroll
        for (int j = 0; j < 8; j++) acc[i][j] = 0.0f;

    for (int k0 = 0; k0 < Kd; k0 += 8) {
        float4 xv = *(const float4*)(Xg + k0);
        float4 wv = *(const float4*)(Wg + k0);
        Xs[lk + 0][lm] = xv.x; Xs[lk + 1][lm] = xv.y;
        Xs[lk + 2][lm] = xv.z; Xs[lk + 3][lm] = xv.w;
        Ws[lk + 0][lm] = wv.x; Ws[lk + 1][lm] = wv.y;
        Ws[lk + 2][lm] = wv.z; Ws[lk + 3][lm] = wv.w;
        __syncthreads();

#pragma unroll
        for (int kk = 0; kk < 8; kk++) {
            float a[8], b[8];
#pragma unroll
            for (int i = 0; i < 8; i++) a[i] = Xs[kk][ty * 8 + i];
#pragma unroll
            for (int j = 0; j < 8; j++) b[j] = Ws[kk][tx * 8 + j];
#pragma unroll
            for (int i = 0; i < 8; i++)
#pragma unroll
                for (int j = 0; j < 8; j++)
                    acc[i][j] = fmaf(a[i], b[j], acc[i][j]);
        }
        __syncthreads();
    }

#pragma unroll
    for (int i = 0; i < 8; i++) {
        const size_t r = (size_t)(row0 + ty * 8 + i);
#pragma unroll
        for (int j = 0; j < 8; j++) {
            const int c = col0 + tx * 8 + j;
            Y[r * N + c] = acc[i][j] + bias[c];
        }
    }
}

// ---------------------------------------------------------------------------
// Flash-style attention, fp32, online softmax.
// Grid: (T/64, H, B). Block: 256 threads (8 warps).
// Each block handles 64 query rows of one (b, h); each warp owns 8 rows.
// KV tile = 32 keys; each lane owns key j = lane within the tile.
// Q/K/V laid out as [B*T, E] with head slice at column h*D (d contiguous).
// ---------------------------------------------------------------------------
constexpr int QT = 64;
constexpr int KT = 32;

__global__ __launch_bounds__(256) void flash_attn(
    const float* __restrict__ Q, const float* __restrict__ K,
    const float* __restrict__ V, float* __restrict__ O)
{
    __shared__ float Qs[QT][68];
    __shared__ float Ks[KT][68];
    __shared__ float Vs[KT][68];

    const int b = blockIdx.z;
    const int h = blockIdx.y;
    const int q0 = blockIdx.x * QT;
    const int tid = threadIdx.x;
    const int warp = tid >> 5;
    const int lane = tid & 31;
    const float scale = 0.125f;  // 1/sqrt(64)

    // Load Q tile: 64 rows x 64 floats = 1024 float4, 4 per thread.
#pragma unroll
    for (int it = 0; it < 4; it++) {
        const int idx = tid + it * 256;
        const int r = idx >> 4;
        const int c4 = idx & 15;
        const float4 v = *(const float4*)(Q + (size_t)(b * cT + q0 + r) * cE + h * cD + c4 * 4);
        *(float4*)(&Qs[r][c4 * 4]) = v;
    }

    float m[8], l[8], o0[8], o1[8];
#pragma unroll
    for (int i = 0; i < 8; i++) { m[i] = -1e30f; l[i] = 0.0f; o0[i] = 0.0f; o1[i] = 0.0f; }
    const int r0 = warp * 8;

    for (int kb = 0; kb < cT; kb += KT) {
        // Load K/V tiles: 32 x 64 floats = 512 float4 each, 2 per thread.
#pragma unroll
        for (int it = 0; it < 2; it++) {
            const int idx = tid + it * 256;
            const int r = idx >> 4;
            const int c4 = idx & 15;
            const size_t goff = (size_t)(b * cT + kb + r) * cE + h * cD + c4 * 4;
            *(float4*)(&Ks[r][c4 * 4]) = *(const float4*)(K + goff);
            *(float4*)(&Vs[r][c4 * 4]) = *(const float4*)(V + goff);
        }
        __syncthreads();

        // Scores: lane owns key j = lane; 8 rows per warp.
        float s[8];
#pragma unroll
        for (int i = 0; i < 8; i++) s[i] = 0.0f;
        const float4* krow = (const float4*)(&Ks[lane][0]);
#pragma unroll
        for (int d4 = 0; d4 < 16; d4++) {
            const float4 kv = krow[d4];
#pragma unroll
            for (int i = 0; i < 8; i++) {
                const float4 qv = *(const float4*)(&Qs[r0 + i][d4 * 4]);
                s[i] += qv.x * kv.x + qv.y * kv.y + qv.z * kv.z + qv.w * kv.w;
            }
        }

        // Online softmax update per row.
        float p[8];
#pragma unroll
        for (int i = 0; i < 8; i++) {
            const float si = s[i] * scale;
            float mx = si;
#pragma unroll
            for (int off = 16; off > 0; off >>= 1)
                mx = fmaxf(mx, __shfl_xor_sync(0xffffffffu, mx, off));
            const float mn = fmaxf(m[i], mx);
            const float corr = __expf(m[i] - mn);
            m[i] = mn;
            p[i] = __expf(si - mn);
            float ps = p[i];
#pragma unroll
            for (int off = 16; off > 0; off >>= 1)
                ps += __shfl_xor_sync(0xffffffffu, ps, off);
            l[i] = l[i] * corr + ps;
            o0[i] *= corr;
            o1[i] *= corr;
        }

        // PV: lane owns output dims d = lane and d = lane + 32.
#pragma unroll
        for (int j = 0; j < KT; j++) {
            const float va = Vs[j][lane];
            const float vb = Vs[j][lane + 32];
#pragma unroll
            for (int i = 0; i < 8; i++) {
                const float pj = __shfl_sync(0xffffffffu, p[i], j);
                o0[i] = fmaf(pj, va, o0[i]);
                o1[i] = fmaf(pj, vb, o1[i]);
            }
        }
        __syncthreads();
    }

    // Epilogue: normalize and store as [B, T, E] (e = h*D + d).
#pragma unroll
    for (int i = 0; i < 8; i++) {
        const float inv = 1.0f / l[i];
        const size_t base = (size_t)(b * cT + q0 + r0 + i) * cE + h * cD;
        O[base + lane]      = o0[i] * inv;
        O[base + lane + 32] = o1[i] * inv;
    }
}

// ---------------------------------------------------------------------------
// kernel_launch: QKV projections -> attention -> output projection.
// All launches on the default stream; graph-capturable; no allocations.
// ---------------------------------------------------------------------------
extern "C" void kernel_launch(void* const* d_in, const int* in_sizes, int n_in,
                              void* d_out, int out_size)
{
    const float* x  = (const float*)d_in[0];
    const float* Wq = (const float*)d_in[1];
    const float* bq = (const float*)d_in[2];
    const float* Wk = (const float*)d_in[3];
    const float* bk = (const float*)d_in[4];
    const float* Wv = (const float*)d_in[5];
    const float* bv = (const float*)d_in[6];
    const float* Wo = (const float*)d_in[7];
    const float* bo = (const float*)d_in[8];
    float* out = (float*)d_out;

    float *gQ, *gK, *gV, *gA;
    cudaGetSymbolAddress((void**)&gQ, g_Q);
    cudaGetSymbolAddress((void**)&gK, g_K);
    cudaGetSymbolAddress((void**)&gV, g_V);
    cudaGetSymbolAddress((void**)&gA, g_A);

    const dim3 gemm_grid(cE / 128, cM / 128);  // (8, 32)

    sgemm_nt_bias<<<gemm_grid, 256>>>(x, Wq, bq, gQ);
    sgemm_nt_bias<<<gemm_grid, 256>>>(x, Wk, bk, gK);
    sgemm_nt_bias<<<gemm_grid, 256>>>(x, Wv, bv, gV);

    flash_attn<<<dim3(cT / QT, cH, cB), 256>>>(gQ, gK, gV, gA);

    sgemm_nt_bias<<<gemm_grid, 256>>>(gA, Wo, bo, out);
}

// round 2
// speedup vs baseline: 3.7180x; 3.7180x over previous
#include <cuda_runtime.h>
#include <cstdint>

// Problem constants
constexpr int cB = 2;
constexpr int cT = 2048;
constexpr int cE = 1024;
constexpr int cH = 16;
constexpr int cD = 64;
constexpr int cM = cB * cT;  // 4096

// Scratch (allocation-free rule -> __device__ globals)
__device__ float g_Q[(size_t)cM * cE];
__device__ float g_K[(size_t)cM * cE];
__device__ float g_V[(size_t)cM * cE];
__device__ float g_A[(size_t)cM * cE];

// ---------------------------------------------------------------------------
// tf32 helpers
// ---------------------------------------------------------------------------
__device__ __forceinline__ uint32_t f2tf(float x) {
    uint32_t r;
    asm("cvt.rna.tf32.f32 %0, %1;" : "=r"(r) : "f"(x));
    return r;
}
__device__ __forceinline__ float ex2(float x) {
    float r;
    asm("ex2.approx.f32 %0, %1;" : "=f"(r) : "f"(x));
    return r;
}
// D += A * B  (m16n8k8 tf32, row.col)
__device__ __forceinline__ void mma_tf32(float* d, const uint32_t* a, const uint32_t* b) {
    asm volatile(
        "mma.sync.aligned.m16n8k8.row.col.f32.tf32.tf32.f32 "
        "{%0,%1,%2,%3}, {%4,%5,%6,%7}, {%8,%9}, {%0,%1,%2,%3};"
        : "+f"(d[0]), "+f"(d[1]), "+f"(d[2]), "+f"(d[3])
        : "r"(a[0]), "r"(a[1]), "r"(a[2]), "r"(a[3]), "r"(b[0]), "r"(b[1]));
}

// ---------------------------------------------------------------------------
// GEMM: Y[M,N] = X[M,K] @ W[N,K]^T + bias.  M=4096, N=K=1024.
// Block 128x128, BK=16, 8 warps (2m x 4n), warp tile 64x32.
// Smem stride 20 -> conflict-free fragment loads ((20g+t) distinct mod 32).
// ---------------------------------------------------------------------------
__global__ __launch_bounds__(256) void gemm_tf32(
    const float* __restrict__ X, const float* __restrict__ W,
    const float* __restrict__ bias, float* __restrict__ Y)
{
    constexpr int Kd = 1024;
    constexpr int N = 1024;
    __shared__ uint32_t Xs[128][20];
    __shared__ uint32_t Ws[128][20];

    const int tid = threadIdx.x;
    const int warp = tid >> 5;
    const int lane = tid & 31;
    const int wm = warp >> 2;   // 0..1
    const int wn = warp & 3;    // 0..3
    const int g = lane >> 2;    // 0..7
    const int t = lane & 3;     // 0..3
    const int row0 = blockIdx.y * 128;
    const int col0 = blockIdx.x * 128;

    float acc[4][4][4];
#pragma unroll
    for (int mf = 0; mf < 4; mf++)
#pragma unroll
        for (int nf = 0; nf < 4; nf++)
#pragma unroll
            for (int r = 0; r < 4; r++) acc[mf][nf][r] = 0.0f;

    for (int k0 = 0; k0 < Kd; k0 += 16) {
        // Load 128x16 tiles of X and W (converted to tf32).
#pragma unroll
        for (int it = 0; it < 2; it++) {
            const int idx = tid + it * 256;       // 0..511
            const int r = idx >> 2;               // 0..127
            const int c4 = idx & 3;               // 0..3
            const float4 xv = *(const float4*)(X + (size_t)(row0 + r) * Kd + k0 + c4 * 4);
            const float4 wv = *(const float4*)(W + (size_t)(col0 + r) * Kd + k0 + c4 * 4);
            uint4 xu, wu;
            xu.x = f2tf(xv.x); xu.y = f2tf(xv.y); xu.z = f2tf(xv.z); xu.w = f2tf(xv.w);
            wu.x = f2tf(wv.x); wu.y = f2tf(wv.y); wu.z = f2tf(wv.z); wu.w = f2tf(wv.w);
            *(uint4*)(&Xs[r][c4 * 4]) = xu;
            *(uint4*)(&Ws[r][c4 * 4]) = wu;
        }
        __syncthreads();

#pragma unroll
        for (int ks = 0; ks < 2; ks++) {
            uint32_t a[4][4], b[4][2];
#pragma unroll
            for (int mf = 0; mf < 4; mf++) {
                const int r = wm * 64 + mf * 16;
                a[mf][0] = Xs[r + g][ks * 8 + t];
                a[mf][1] = Xs[r + g + 8][ks * 8 + t];
                a[mf][2] = Xs[r + g][ks * 8 + t + 4];
                a[mf][3] = Xs[r + g + 8][ks * 8 + t + 4];
            }
#pragma unroll
            for (int nf = 0; nf < 4; nf++) {
                const int c = wn * 32 + nf * 8;
                b[nf][0] = Ws[c + g][ks * 8 + t];
                b[nf][1] = Ws[c + g][ks * 8 + t + 4];
            }
#pragma unroll
            for (int mf = 0; mf < 4; mf++)
#pragma unroll
                for (int nf = 0; nf < 4; nf++)
                    mma_tf32(acc[mf][nf], a[mf], b[nf]);
        }
        __syncthreads();
    }

    // Epilogue: add bias, float2 stores.
#pragma unroll
    for (int mf = 0; mf < 4; mf++) {
        const int r = row0 + wm * 64 + mf * 16 + g;
#pragma unroll
        for (int nf = 0; nf < 4; nf++) {
            const int c = col0 + wn * 32 + nf * 8 + 2 * t;
            const float bx = bias[c];
            const float by = bias[c + 1];
            float2 v0, v1;
            v0.x = acc[mf][nf][0] + bx; v0.y = acc[mf][nf][1] + by;
            v1.x = acc[mf][nf][2] + bx; v1.y = acc[mf][nf][3] + by;
            *(float2*)(Y + (size_t)r * N + c) = v0;
            *(float2*)(Y + (size_t)(r + 8) * N + c) = v1;
        }
    }
}

// ---------------------------------------------------------------------------
// Flash attention with tf32 MMA.
// Grid (T/64, H, B), 128 threads (4 warps). Warp owns 16 q rows.
// KV tile = 32 keys. Q fragments register-resident for all tiles.
// Ks stride 68, Vs stride 72, Ps stride 36: all fragment reads conflict-free.
// ---------------------------------------------------------------------------
__global__ __launch_bounds__(128) void flash_tf32(
    const float* __restrict__ Q, const float* __restrict__ K,
    const float* __restrict__ V, float* __restrict__ O)
{
    __shared__ uint32_t Ks[32][68];
    __shared__ uint32_t Vs[32][72];
    __shared__ uint32_t Ps[4][16][36];

    const int tid = threadIdx.x;
    const int warp = tid >> 5;
    const int lane = tid & 31;
    const int g = lane >> 2;
    const int t = lane & 3;
    const int b = blockIdx.z;
    const int h = blockIdx.y;
    const int q0 = blockIdx.x * 64;
    const float sl = 0.125f * 1.4426950408889634f;  // (1/sqrt(D)) * log2(e)

    // Q fragments: rows q0 + warp*16 + {g, g+8}, cols ks*8 + {t, t+4}.
    uint32_t qf[8][4];
    const float* Qb = Q + (size_t)(b * cT + q0 + warp * 16) * cE + h * cD;
#pragma unroll
    for (int ks = 0; ks < 8; ks++) {
        qf[ks][0] = f2tf(Qb[(size_t)g * cE + ks * 8 + t]);
        qf[ks][1] = f2tf(Qb[(size_t)(g + 8) * cE + ks * 8 + t]);
        qf[ks][2] = f2tf(Qb[(size_t)g * cE + ks * 8 + t + 4]);
        qf[ks][3] = f2tf(Qb[(size_t)(g + 8) * cE + ks * 8 + t + 4]);
    }

    float out[8][4];
#pragma unroll
    for (int nf = 0; nf < 8; nf++)
#pragma unroll
        for (int r = 0; r < 4; r++) out[nf][r] = 0.0f;
    float m0 = -1e30f, m1 = -1e30f, l0 = 0.0f, l1 = 0.0f;

    for (int kb = 0; kb < cT; kb += 32) {
        // Load K/V tile (32 keys x 64 dims), convert to tf32.
#pragma unroll
        for (int it = 0; it < 4; it++) {
            const int idx = tid + it * 128;
            const int key = idx >> 4;
            const int d4 = idx & 15;
            const size_t goff = (size_t)(b * cT + kb + key) * cE + h * cD + d4 * 4;
            const float4 kv = *(const float4*)(K + goff);
            const float4 vv = *(const float4*)(V + goff);
            uint4 ku, vu;
            ku.x = f2tf(kv.x); ku.y = f2tf(kv.y); ku.z = f2tf(kv.z); ku.w = f2tf(kv.w);
            vu.x = f2tf(vv.x); vu.y = f2tf(vv.y); vu.z = f2tf(vv.z); vu.w = f2tf(vv.w);
            *(uint4*)(&Ks[key][d4 * 4]) = ku;
            *(uint4*)(&Vs[key][d4 * 4]) = vu;
        }
        __syncthreads();

        // Scores: S = Q K^T, 4 n-frags (32 keys) x 8 k-steps (d=64).
        float s[4][4];
#pragma unroll
        for (int nf = 0; nf < 4; nf++)
#pragma unroll
            for (int r = 0; r < 4; r++) s[nf][r] = 0.0f;
#pragma unroll
        for (int ks = 0; ks < 8; ks++) {
#pragma unroll
            for (int nf = 0; nf < 4; nf++) {
                uint32_t bf[2];
                bf[0] = Ks[nf * 8 + g][ks * 8 + t];
                bf[1] = Ks[nf * 8 + g][ks * 8 + t + 4];
                mma_tf32(s[nf], qf[ks], bf);
            }
        }

        // Online softmax. Lane holds rows {g, g+8}, cols 2t,2t+1 per n-frag.
        float rmax0 = -1e30f, rmax1 = -1e30f;
#pragma unroll
        for (int nf = 0; nf < 4; nf++) {
            rmax0 = fmaxf(rmax0, fmaxf(s[nf][0], s[nf][1]));
            rmax1 = fmaxf(rmax1, fmaxf(s[nf][2], s[nf][3]));
        }
        rmax0 = fmaxf(rmax0, __shfl_xor_sync(0xffffffffu, rmax0, 1));
        rmax0 = fmaxf(rmax0, __shfl_xor_sync(0xffffffffu, rmax0, 2));
        rmax1 = fmaxf(rmax1, __shfl_xor_sync(0xffffffffu, rmax1, 1));
        rmax1 = fmaxf(rmax1, __shfl_xor_sync(0xffffffffu, rmax1, 2));

        const float mn0 = fmaxf(m0, rmax0 * sl);
        const float mn1 = fmaxf(m1, rmax1 * sl);
        const float c0 = ex2(m0 - mn0);
        const float c1 = ex2(m1 - mn1);
        m0 = mn0; m1 = mn1;

        float rs0 = 0.0f, rs1 = 0.0f;
#pragma unroll
        for (int nf = 0; nf < 4; nf++) {
            const float p00 = ex2(fmaf(s[nf][0], sl, -mn0));
            const float p01 = ex2(fmaf(s[nf][1], sl, -mn0));
            const float p10 = ex2(fmaf(s[nf][2], sl, -mn1));
            const float p11 = ex2(fmaf(s[nf][3], sl, -mn1));
            rs0 += p00 + p01;
            rs1 += p10 + p11;
            uint2 u0, u1;
            u0.x = f2tf(p00); u0.y = f2tf(p01);
            u1.x = f2tf(p10); u1.y = f2tf(p11);
            *(uint2*)(&Ps[warp][g][nf * 8 + 2 * t]) = u0;
            *(uint2*)(&Ps[warp][g + 8][nf * 8 + 2 * t]) = u1;
        }
        rs0 += __shfl_xor_sync(0xffffffffu, rs0, 1);
        rs0 += __shfl_xor_sync(0xffffffffu, rs0, 2);
        rs1 += __shfl_xor_sync(0xffffffffu, rs1, 1);
        rs1 += __shfl_xor_sync(0xffffffffu, rs1, 2);
        l0 = l0 * c0 + rs0;
        l1 = l1 * c1 + rs1;
#pragma unroll
        for (int nf = 0; nf < 8; nf++) {
            out[nf][0] *= c0; out[nf][1] *= c0;
            out[nf][2] *= c1; out[nf][3] *= c1;
        }
        __syncwarp();

        // PV: out += P (16 x 32) * V (32 x 64). 4 k-steps, 8 n-frags.
#pragma unroll
        for (int ks = 0; ks < 4; ks++) {
            uint32_t pa[4];
            pa[0] = Ps[warp][g][ks * 8 + t];
            pa[1] = Ps[warp][g + 8][ks * 8 + t];
            pa[2] = Ps[warp][g][ks * 8 + t + 4];
            pa[3] = Ps[warp][g + 8][ks * 8 + t + 4];
#pragma unroll
            for (int nf = 0; nf < 8; nf++) {
                uint32_t bf[2];
                bf[0] = Vs[ks * 8 + t][nf * 8 + g];
                bf[1] = Vs[ks * 8 + t + 4][nf * 8 + g];
                mma_tf32(out[nf], pa, bf);
            }
        }
        __syncthreads();
    }

    // Epilogue: normalize, store [B,T,E].
    const float inv0 = 1.0f / l0;
    const float inv1 = 1.0f / l1;
    float* Ob = O + (size_t)(b * cT + q0 + warp * 16) * cE + h * cD;
#pragma unroll
    for (int nf = 0; nf < 8; nf++) {
        const int dc = nf * 8 + 2 * t;
        float2 v0, v1;
        v0.x = out[nf][0] * inv0; v0.y = out[nf][1] * inv0;
        v1.x = out[nf][2] * inv1; v1.y = out[nf][3] * inv1;
        *(float2*)(Ob + (size_t)g * cE + dc) = v0;
        *(float2*)(Ob + (size_t)(g + 8) * cE + dc) = v1;
    }
}

// ---------------------------------------------------------------------------
extern "C" void kernel_launch(void* const* d_in, const int* in_sizes, int n_in,
                              void* d_out, int out_size)
{
    const float* x  = (const float*)d_in[0];
    const float* Wq = (const float*)d_in[1];
    const float* bq = (const float*)d_in[2];
    const float* Wk = (const float*)d_in[3];
    const float* bk = (const float*)d_in[4];
    const float* Wv = (const float*)d_in[5];
    const float* bv = (const float*)d_in[6];
    const float* Wo = (const float*)d_in[7];
    const float* bo = (const float*)d_in[8];
    float* out = (float*)d_out;

    float *gQ, *gK, *gV, *gA;
    cudaGetSymbolAddress((void**)&gQ, g_Q);
    cudaGetSymbolAddress((void**)&gK, g_K);
    cudaGetSymbolAddress((void**)&gV, g_V);
    cudaGetSymbolAddress((void**)&gA, g_A);

    const dim3 gemm_grid(cE / 128, cM / 128);  // (8, 32)

    gemm_tf32<<<gemm_grid, 256>>>(x, Wq, bq, gQ);
    gemm_tf32<<<gemm_grid, 256>>>(x, Wk, bk, gK);
    gemm_tf32<<<gemm_grid, 256>>>(x, Wv, bv, gV);

    flash_tf32<<<dim3(cT / 64, cH, cB), 128>>>(gQ, gK, gV, gA);

    gemm_tf32<<<gemm_grid, 256>>>(gA, Wo, bo, out);
}